// round 12
// baseline (speedup 1.0000x reference)
#include <cuda_runtime.h>
#include <math_constants.h>

#define FULL 0xffffffffu

// One warp per ray, 8 warps/block.
// Per-warp smem words: [0..62]=cdf, [63]=INF pad, [64..191]=fine, [192]=INF.
// After merge, [0..191] reused as per-sample weights.
__global__ __launch_bounds__(256) void render_ray_kernel(
    const float* __restrict__ cdv,   // [B,64] uniform grid NEAR + k*step
    const float* __restrict__ cw,    // [B,64]
    const float* __restrict__ uin,   // [B,128]
    const float* __restrict__ den,   // [B,192]
    const float* __restrict__ col,   // [B,192,3]
    float* __restrict__ out,         // [B,3]
    int B)
{
    const int warp = threadIdx.x >> 5;
    const int lane = threadIdx.x & 31;
    const int ray  = blockIdx.x * 8 + warp;
    if (ray >= B) return;

    __shared__ float sh[8][200];     // 800B/warp, 16B-aligned per warp
    float* base  = sh[warp];
    float* cdfs  = base;          // cdf[0..62], [63]=INF sentinel
    float* fineS = base + 64;     // fine[0..127], sentinel at base[192]
    float* wsh   = base;          // 192 weights (reuse after merge)

    // ---- uniform grid params: only cdv[0], cdv[1] needed ----
    float2 c2 = make_float2(0.f, 0.f);
    if (lane == 0) c2 = *reinterpret_cast<const float2*>(cdv + (size_t)ray * 64);
    const float NEARv = __shfl_sync(FULL, c2.x, 0);
    const float step  = __shfl_sync(FULL, c2.y, 0) - NEARv;
    const float M0    = NEARv + 0.5f * step;     // mids[k] = M0 + k*step
    if (lane == 0) cdfs[63]  = CUDART_INF_F;     // cdf pad for unguarded search
    if (lane == 1) base[192] = CUDART_INF_F;     // fine sentinel

    // ---- weights -> normalized CDF (62 pdf entries, cdf[0..62]) ----
    const float* cwp = cw + (size_t)ray * 64;
    float w0 = 0.f, w1 = 0.f;
    if (lane < 31) {
        w0 = cwp[1 + 2 * lane] + 1e-5f;
        w1 = cwp[2 + 2 * lane] + 1e-5f;
    }
    float s2 = w0 + w1;
    float inc = s2;
    #pragma unroll
    for (int off = 1; off < 32; off <<= 1) {
        float v = __shfl_up_sync(FULL, inc, off);
        if (lane >= off) inc += v;
    }
    float total = __shfl_sync(FULL, inc, 31);
    float excl0 = inc - s2;
    float rt    = __fdividef(1.0f, total);
    if (lane == 0) cdfs[0] = 0.f;
    if (lane < 31) {
        cdfs[2 * lane + 1] = (excl0 + w0) * rt;
        cdfs[2 * lane + 2] = (excl0 + w0 + w1) * rt;
    }

    // ---- load u (4/lane blocked) and bitonic sort 128 ----
    const float4 u4 = reinterpret_cast<const float4*>(uin + (size_t)ray * 128)[lane];
    float r[4] = { u4.x, u4.y, u4.z, u4.w };
    const int ebase = lane * 4;

    #pragma unroll
    for (int k = 2; k <= 128; k <<= 1) {
        #pragma unroll
        for (int d = k >> 1; d > 0; d >>= 1) {
            if (d >= 4) {
                const bool flip = (((ebase & k) == 0) != ((ebase & d) != 0));
                #pragma unroll
                for (int j = 0; j < 4; j++) {
                    float o = __shfl_xor_sync(FULL, r[j], d >> 2);
                    r[j] = flip ? fminf(r[j], o) : fmaxf(r[j], o);
                }
            } else {
                #pragma unroll
                for (int j = 0; j < 4; j++) {
                    int jp = j ^ d;
                    if (jp > j) {
                        bool asc = (((ebase + j) & k) == 0);
                        float lo2 = fminf(r[j], r[jp]);
                        float hi2 = fmaxf(r[j], r[jp]);
                        r[j]  = asc ? lo2 : hi2;
                        r[jp] = asc ? hi2 : lo2;
                    }
                }
            }
        }
    }

    __syncwarp();  // cdf + sentinels visible

    // ---- inverse CDF: unguarded power-of-2 count search (6 probes) ----
    // counts entries of cdf[0..62] <= u; cdf[63]=INF pad. c >= 1 since cdf[0]=0.
    #pragma unroll
    for (int j = 0; j < 4; j++) {
        float uv = r[j];
        int c = 0;
        #pragma unroll
        for (int w = 32; w; w >>= 1)
            c += (cdfs[c + w - 1] <= uv) ? w : 0;
        float cb = cdfs[c - 1];
        float ca = cdfs[c];               // c==63 -> INF -> t==0, clamps to last mid
        float dnm = ca - cb;
        if (dnm < 1e-5f) dnm = 1.f;
        float t = __fdividef(uv - cb, dnm);
        r[j] = fmaf(__int2float_rn(c - 1) + t, step, M0);   // reuse r[] as fine depth
    }
    // single conflict-free vector store (4 wavefronts instead of 16)
    reinterpret_cast<float4*>(fineS)[lane] = make_float4(r[0], r[1], r[2], r[3]);
    __syncwarp();

    // ---- merge-path: arithmetic coarse (NEAR + i*step) + fine[128] -> 6 regs ----
    float m[6];
    {
        const int d0  = lane * 6;
        const int hib = min(d0, 64);
        int c = max(0, d0 - 128);
        #pragma unroll
        for (int w = 64; w; w >>= 1) {
            int idx = c + w - 1;
            float a = fmaf(__int2float_rn(idx), step, NEARv);
            float b = base[64 + d0 - 1 - idx];   // in-bounds; junk guarded below
            bool ok = (idx < hib) && (a <= b);
            c += ok ? w : 0;
        }
        int jb = d0 - c;                 // fine cursor (0..128)
        float fia = __int2float_rn(c);   // coarse cursor as float
        float a = fmaf(fia, step, NEARv);   // index 64 acts as natural sentinel
        float b = base[64 + jb];            // jb==128 -> INF sentinel
        #pragma unroll
        for (int t = 0; t < 6; t++) {
            bool ta = (a <= b);
            m[t] = ta ? a : b;
            fia += ta ? 1.0f : 0.0f;
            jb  += ta ? 0 : 1;
            a = fmaf(fia, step, NEARv);
            b = base[64 + jb];
        }
    }
    __syncwarp();   // all fine reads done; base[] safe to reuse

    float m6 = __shfl_down_sync(FULL, m[0], 1);

    // ---- densities: blocked, 3x LDG.64 per lane ----
    const float* dp = den + (size_t)ray * 192 + 6 * lane;
    float2 d01 = reinterpret_cast<const float2*>(dp)[0];
    float2 d23 = reinterpret_cast<const float2*>(dp + 2)[0];
    float2 d45 = reinterpret_cast<const float2*>(dp + 4)[0];

    float x0 = d01.x * (m[1] - m[0]);
    float x1 = x0 + d01.y * (m[2] - m[1]);
    float x2 = x1 + d23.x * (m[3] - m[2]);
    float x3 = x2 + d23.y * (m[4] - m[3]);
    float x4 = x3 + d45.x * (m[5] - m[4]);
    float lastDist = (lane == 31) ? 1e10f : (m6 - m[5]);
    float x5 = x4 + d45.y * lastDist;

    // Lane 31: exclude the artificial 1e10 term from the scan value
    // (prevents catastrophic cancellation in Sx; e5 still uses full x5 -> 0).
    float xs = (lane == 31) ? x4 : x5;

    float tinc = xs;
    #pragma unroll
    for (int off = 1; off < 32; off <<= 1) {
        float v = __shfl_up_sync(FULL, tinc, off);
        if (lane >= off) tinc += v;
    }
    float Sx = tinc - xs;   // exclusive prefix (sum of lanes < me)

    float e0p = __expf(-Sx);
    float e0 = __expf(-(Sx + x0));
    float e1 = __expf(-(Sx + x1));
    float e2 = __expf(-(Sx + x2));
    float e3 = __expf(-(Sx + x3));
    float e4 = __expf(-(Sx + x4));
    float e5 = __expf(-(Sx + x5));

    // weight stores as 3x STS.64 (conflict-free per phase): 6 wavefronts vs 12
    {
        float2* w2 = reinterpret_cast<float2*>(wsh + 6 * lane);  // 24B stride, 8B aligned
        w2[0] = make_float2(e0p - e0, e0 - e1);
        w2[1] = make_float2(e1 - e2, e2 - e3);
        w2[2] = make_float2(e3 - e4, e4 - e5);
    }
    __syncwarp();

    // ---- color accumulation: coalesced loads, div-free weight indexing ----
    // j = 32t + lane; floor(j/3) = 10t + (2t)/3 + L + carry
    const int L  = lane / 3;          // lane = 3L + p
    const int p  = lane - 3 * L;
    const float* wp0 = wsh + L;                 // R=0: carry 0
    const float* wp1 = wsh + L + (p >= 1);      // R=2: carry = (p>=1)
    const float* wp2 = wsh + L + (p >= 2);      // R=1: carry = (p>=2)

    const float* colp = col + (size_t)ray * 576;
    float a0 = 0.f, a1 = 0.f, a2 = 0.f;
    #pragma unroll
    for (int t = 0; t < 18; t++) {
        float v = colp[32 * t + lane];
        const int R = (2 * t) % 3;              // compile-time
        const int C = 10 * t + (2 * t) / 3;     // compile-time
        float wv = (R == 0) ? wp0[C] : ((R == 1) ? wp2[C] : wp1[C]);
        if (R == 0) a0 += wv * v;
        else if (R == 1) a1 += wv * v;
        else a2 += wv * v;
    }

    // lane's a[k] holds channel (p + k) % 3
    float rr = (p == 0) ? a0 : ((p == 1) ? a2 : a1);
    float gg = (p == 0) ? a1 : ((p == 1) ? a0 : a2);
    float bb = (p == 0) ? a2 : ((p == 1) ? a1 : a0);

    #pragma unroll
    for (int off = 16; off; off >>= 1) {
        rr += __shfl_down_sync(FULL, rr, off);
        gg += __shfl_down_sync(FULL, gg, off);
        bb += __shfl_down_sync(FULL, bb, off);
    }
    if (lane == 0) {
        out[(size_t)ray * 3 + 0] = rr;
        out[(size_t)ray * 3 + 1] = gg;
        out[(size_t)ray * 3 + 2] = bb;
    }
}

extern "C" void kernel_launch(void* const* d_in, const int* in_sizes, int n_in,
                              void* d_out, int out_size)
{
    const float* cdv = (const float*)d_in[2];
    const float* cw  = (const float*)d_in[3];
    const float* u   = (const float*)d_in[4];
    const float* den = (const float*)d_in[5];
    const float* col = (const float*)d_in[6];
    float* out = (float*)d_out;
    const int B = in_sizes[0] / 3;

    const int warpsPerBlock = 8;
    const int blocks = (B + warpsPerBlock - 1) / warpsPerBlock;
    render_ray_kernel<<<blocks, warpsPerBlock * 32>>>(cdv, cw, u, den, col, out, B);
}

// round 13
// speedup vs baseline: 1.0260x; 1.0260x over previous
#include <cuda_runtime.h>
#include <math_constants.h>

#define FULL 0xffffffffu

// One warp per ray, 8 warps/block.
// Per-warp smem words: [0..62]=cdf, [63]=INF pad, [64..191]=fine, [192]=INF.
// After merge, [0..191] reused as per-sample weights.
__global__ __launch_bounds__(256, 8) void render_ray_kernel(
    const float* __restrict__ cdv,   // [B,64] uniform grid NEAR + k*step
    const float* __restrict__ cw,    // [B,64]
    const float* __restrict__ uin,   // [B,128]
    const float* __restrict__ den,   // [B,192]
    const float* __restrict__ col,   // [B,192,3]
    float* __restrict__ out,         // [B,3]
    int B)
{
    const int warp = threadIdx.x >> 5;
    const int lane = threadIdx.x & 31;
    const int ray  = blockIdx.x * 8 + warp;
    if (ray >= B) return;

    __shared__ float sh[8][200];     // 800B/warp, 16B-aligned per warp
    float* base  = sh[warp];
    float* cdfs  = base;          // cdf[0..62], [63]=INF sentinel
    float* fineS = base + 64;     // fine[0..127], sentinel at base[192]
    float* wsh   = base;          // 192 weights (reuse after merge)

    // ---- uniform grid params: only cdv[0], cdv[1] needed ----
    float2 c2 = make_float2(0.f, 0.f);
    if (lane == 0) c2 = *reinterpret_cast<const float2*>(cdv + (size_t)ray * 64);
    const float NEARv = __shfl_sync(FULL, c2.x, 0);
    const float step  = __shfl_sync(FULL, c2.y, 0) - NEARv;
    const float M0    = NEARv + 0.5f * step;     // mids[k] = M0 + k*step
    if (lane == 0) cdfs[63]  = CUDART_INF_F;     // cdf pad for unguarded search
    if (lane == 1) base[192] = CUDART_INF_F;     // fine sentinel

    // ---- weights -> normalized CDF (62 pdf entries, cdf[0..62]) ----
    const float* cwp = cw + (size_t)ray * 64;
    float w0 = 0.f, w1 = 0.f;
    if (lane < 31) {
        w0 = cwp[1 + 2 * lane] + 1e-5f;
        w1 = cwp[2 + 2 * lane] + 1e-5f;
    }
    float s2 = w0 + w1;
    float inc = s2;
    #pragma unroll
    for (int off = 1; off < 32; off <<= 1) {
        float v = __shfl_up_sync(FULL, inc, off);
        if (lane >= off) inc += v;
    }
    float total = __shfl_sync(FULL, inc, 31);
    float excl0 = inc - s2;
    float rt    = __fdividef(1.0f, total);
    if (lane == 0) cdfs[0] = 0.f;
    if (lane < 31) {
        cdfs[2 * lane + 1] = (excl0 + w0) * rt;
        cdfs[2 * lane + 2] = (excl0 + w0 + w1) * rt;
    }

    // ---- load u (4/lane blocked) and bitonic sort 128 ----
    const float4 u4 = reinterpret_cast<const float4*>(uin + (size_t)ray * 128)[lane];
    float r[4] = { u4.x, u4.y, u4.z, u4.w };
    const int ebase = lane * 4;

    #pragma unroll
    for (int k = 2; k <= 128; k <<= 1) {
        #pragma unroll
        for (int d = k >> 1; d > 0; d >>= 1) {
            if (d >= 4) {
                const bool flip = (((ebase & k) == 0) != ((ebase & d) != 0));
                #pragma unroll
                for (int j = 0; j < 4; j++) {
                    float o = __shfl_xor_sync(FULL, r[j], d >> 2);
                    r[j] = flip ? fminf(r[j], o) : fmaxf(r[j], o);
                }
            } else {
                #pragma unroll
                for (int j = 0; j < 4; j++) {
                    int jp = j ^ d;
                    if (jp > j) {
                        bool asc = (((ebase + j) & k) == 0);
                        float lo2 = fminf(r[j], r[jp]);
                        float hi2 = fmaxf(r[j], r[jp]);
                        r[j]  = asc ? lo2 : hi2;
                        r[jp] = asc ? hi2 : lo2;
                    }
                }
            }
        }
    }

    __syncwarp();  // cdf + sentinels visible

    // ---- inverse CDF: unguarded power-of-2 count search (6 probes) ----
    // counts entries of cdf[0..62] <= u; cdf[63]=INF pad. c >= 1 since cdf[0]=0.
    #pragma unroll
    for (int j = 0; j < 4; j++) {
        float uv = r[j];
        int c = 0;
        #pragma unroll
        for (int w = 32; w; w >>= 1)
            c += (cdfs[c + w - 1] <= uv) ? w : 0;
        float cb = cdfs[c - 1];
        float ca = cdfs[c];               // c==63 -> INF -> t==0, clamps to last mid
        float dnm = ca - cb;
        if (dnm < 1e-5f) dnm = 1.f;
        float t = __fdividef(uv - cb, dnm);
        r[j] = fmaf(__int2float_rn(c - 1) + t, step, M0);   // reuse r[] as fine depth
    }
    // single conflict-free vector store (4 wavefronts instead of 16)
    reinterpret_cast<float4*>(fineS)[lane] = make_float4(r[0], r[1], r[2], r[3]);
    __syncwarp();

    // ---- merge-path: arithmetic coarse (NEAR + i*step) + fine[128] -> 6 regs ----
    float m[6];
    {
        const int d0  = lane * 6;
        const int hib = min(d0, 64);
        int c = max(0, d0 - 128);
        #pragma unroll
        for (int w = 64; w; w >>= 1) {
            int idx = c + w - 1;
            float a = fmaf(__int2float_rn(idx), step, NEARv);
            float b = base[64 + d0 - 1 - idx];   // in-bounds; junk guarded below
            bool ok = (idx < hib) && (a <= b);
            c += ok ? w : 0;
        }
        int jb = d0 - c;                 // fine cursor (0..128)
        float fia = __int2float_rn(c);   // coarse cursor as float
        float a = fmaf(fia, step, NEARv);   // index 64 acts as natural sentinel
        float b = base[64 + jb];            // jb==128 -> INF sentinel
        #pragma unroll
        for (int t = 0; t < 6; t++) {
            bool ta = (a <= b);
            m[t] = ta ? a : b;
            fia += ta ? 1.0f : 0.0f;
            jb  += ta ? 0 : 1;
            a = fmaf(fia, step, NEARv);
            b = base[64 + jb];
        }
    }
    __syncwarp();   // all fine reads done; base[] safe to reuse

    float m6 = __shfl_down_sync(FULL, m[0], 1);

    // ---- densities: blocked, 3x LDG.64 per lane ----
    const float* dp = den + (size_t)ray * 192 + 6 * lane;
    float2 d01 = reinterpret_cast<const float2*>(dp)[0];
    float2 d23 = reinterpret_cast<const float2*>(dp + 2)[0];
    float2 d45 = reinterpret_cast<const float2*>(dp + 4)[0];

    float x0 = d01.x * (m[1] - m[0]);
    float x1 = x0 + d01.y * (m[2] - m[1]);
    float x2 = x1 + d23.x * (m[3] - m[2]);
    float x3 = x2 + d23.y * (m[4] - m[3]);
    float x4 = x3 + d45.x * (m[5] - m[4]);
    float lastDist = (lane == 31) ? 1e10f : (m6 - m[5]);
    float x5 = x4 + d45.y * lastDist;

    // Lane 31: exclude the artificial 1e10 term from the scan value
    // (prevents catastrophic cancellation in Sx; e5 still uses full x5 -> 0).
    float xs = (lane == 31) ? x4 : x5;

    float tinc = xs;
    #pragma unroll
    for (int off = 1; off < 32; off <<= 1) {
        float v = __shfl_up_sync(FULL, tinc, off);
        if (lane >= off) tinc += v;
    }
    float Sx = tinc - xs;   // exclusive prefix (sum of lanes < me)

    float e0p = __expf(-Sx);
    float e0 = __expf(-(Sx + x0));
    float e1 = __expf(-(Sx + x1));
    float e2 = __expf(-(Sx + x2));
    float e3 = __expf(-(Sx + x3));
    float e4 = __expf(-(Sx + x4));
    float e5 = __expf(-(Sx + x5));

    const int wb = 6 * lane;
    wsh[wb + 0] = e0p - e0;
    wsh[wb + 1] = e0 - e1;
    wsh[wb + 2] = e1 - e2;
    wsh[wb + 3] = e2 - e3;
    wsh[wb + 4] = e3 - e4;
    wsh[wb + 5] = e4 - e5;
    __syncwarp();

    // ---- color accumulation: coalesced loads, div-free weight indexing ----
    // j = 32t + lane; floor(j/3) = 10t + (2t)/3 + L + carry
    const int L  = lane / 3;          // lane = 3L + p
    const int p  = lane - 3 * L;
    const float* wp0 = wsh + L;                 // R=0: carry 0
    const float* wp1 = wsh + L + (p >= 1);      // R=2: carry = (p>=1)
    const float* wp2 = wsh + L + (p >= 2);      // R=1: carry = (p>=2)

    const float* colp = col + (size_t)ray * 576;
    float a0 = 0.f, a1 = 0.f, a2 = 0.f;
    #pragma unroll
    for (int t = 0; t < 18; t++) {
        float v = colp[32 * t + lane];
        const int R = (2 * t) % 3;              // compile-time
        const int C = 10 * t + (2 * t) / 3;     // compile-time
        float wv = (R == 0) ? wp0[C] : ((R == 1) ? wp2[C] : wp1[C]);
        if (R == 0) a0 += wv * v;
        else if (R == 1) a1 += wv * v;
        else a2 += wv * v;
    }

    // lane's a[k] holds channel (p + k) % 3
    float rr = (p == 0) ? a0 : ((p == 1) ? a2 : a1);
    float gg = (p == 0) ? a1 : ((p == 1) ? a0 : a2);
    float bb = (p == 0) ? a2 : ((p == 1) ? a1 : a0);

    #pragma unroll
    for (int off = 16; off; off >>= 1) {
        rr += __shfl_down_sync(FULL, rr, off);
        gg += __shfl_down_sync(FULL, gg, off);
        bb += __shfl_down_sync(FULL, bb, off);
    }
    if (lane == 0) {
        out[(size_t)ray * 3 + 0] = rr;
        out[(size_t)ray * 3 + 1] = gg;
        out[(size_t)ray * 3 + 2] = bb;
    }
}

extern "C" void kernel_launch(void* const* d_in, const int* in_sizes, int n_in,
                              void* d_out, int out_size)
{
    const float* cdv = (const float*)d_in[2];
    const float* cw  = (const float*)d_in[3];
    const float* u   = (const float*)d_in[4];
    const float* den = (const float*)d_in[5];
    const float* col = (const float*)d_in[6];
    float* out = (float*)d_out;
    const int B = in_sizes[0] / 3;

    const int warpsPerBlock = 8;
    const int blocks = (B + warpsPerBlock - 1) / warpsPerBlock;
    render_ray_kernel<<<blocks, warpsPerBlock * 32>>>(cdv, cw, u, den, col, out, B);
}

// round 14
// speedup vs baseline: 1.0940x; 1.0663x over previous
#include <cuda_runtime.h>
#include <math_constants.h>

#define FULL 0xffffffffu

// One warp per ray, 8 warps/block.
// Per-warp smem words: [0..62]=cdf, [63]=INF pad, [64..191]=fine, [192]=INF.
// After merge, [0..191] reused as per-sample weights.
__global__ __launch_bounds__(256) void render_ray_kernel(
    const float* __restrict__ cdv,   // [B,64] uniform grid NEAR + k*step
    const float* __restrict__ cw,    // [B,64]
    const float* __restrict__ uin,   // [B,128]
    const float* __restrict__ den,   // [B,192]
    const float* __restrict__ col,   // [B,192,3]
    float* __restrict__ out,         // [B,3]
    int B)
{
    const int warp = threadIdx.x >> 5;
    const int lane = threadIdx.x & 31;
    const int ray  = blockIdx.x * 8 + warp;
    if (ray >= B) return;

    __shared__ float sh[8][200];
    float* base  = sh[warp];
    float* cdfs  = base;          // cdf[0..62], [63]=INF pad
    float* fineS = base + 64;     // fine[0..127], sentinel at base[192]
    float* wsh   = base;          // 192 weights (reuse after merge)

    // ---- uniform grid params: only cdv[0], cdv[1] needed ----
    float2 c2 = make_float2(0.f, 0.f);
    if (lane == 0) c2 = *reinterpret_cast<const float2*>(cdv + (size_t)ray * 64);
    const float NEARv = __shfl_sync(FULL, c2.x, 0);
    const float step  = __shfl_sync(FULL, c2.y, 0) - NEARv;
    const float M0    = NEARv + 0.5f * step;     // mids[k] = M0 + k*step
    if (lane == 0) cdfs[63]  = CUDART_INF_F;     // cdf pad for unguarded search
    if (lane == 1) base[192] = CUDART_INF_F;     // fine sentinel

    // ---- weights -> normalized CDF (62 pdf entries, cdf[0..62]) ----
    const float* cwp = cw + (size_t)ray * 64;
    float w0 = 0.f, w1 = 0.f;
    if (lane < 31) {
        w0 = cwp[1 + 2 * lane] + 1e-5f;
        w1 = cwp[2 + 2 * lane] + 1e-5f;
    }
    float s2 = w0 + w1;
    float inc = s2;
    #pragma unroll
    for (int off = 1; off < 32; off <<= 1) {
        float v = __shfl_up_sync(FULL, inc, off);
        if (lane >= off) inc += v;
    }
    float total = __shfl_sync(FULL, inc, 31);
    float excl0 = inc - s2;
    float rt    = __fdividef(1.0f, total);
    if (lane == 0) cdfs[0] = 0.f;
    if (lane < 31) {
        cdfs[2 * lane + 1] = (excl0 + w0) * rt;
        cdfs[2 * lane + 2] = (excl0 + w0 + w1) * rt;
    }

    // ---- load u (4/lane blocked) and bitonic sort 128 ----
    const float4 u4 = reinterpret_cast<const float4*>(uin + (size_t)ray * 128)[lane];
    float r[4] = { u4.x, u4.y, u4.z, u4.w };
    const int ebase = lane * 4;

    #pragma unroll
    for (int k = 2; k <= 128; k <<= 1) {
        #pragma unroll
        for (int d = k >> 1; d > 0; d >>= 1) {
            if (d >= 4) {
                const bool flip = (((ebase & k) == 0) != ((ebase & d) != 0));
                #pragma unroll
                for (int j = 0; j < 4; j++) {
                    float o = __shfl_xor_sync(FULL, r[j], d >> 2);
                    r[j] = flip ? fminf(r[j], o) : fmaxf(r[j], o);
                }
            } else {
                #pragma unroll
                for (int j = 0; j < 4; j++) {
                    int jp = j ^ d;
                    if (jp > j) {
                        bool asc = (((ebase + j) & k) == 0);
                        float lo2 = fminf(r[j], r[jp]);
                        float hi2 = fmaxf(r[j], r[jp]);
                        r[j]  = asc ? lo2 : hi2;
                        r[jp] = asc ? hi2 : lo2;
                    }
                }
            }
        }
    }

    __syncwarp();  // cdf + sentinels visible

    // ---- inverse CDF: unguarded power-of-2 count search (6 probes) ----
    // counts entries of cdf[0..62] <= u; cdf[63]=INF pad. c >= 1 since cdf[0]=0.
    #pragma unroll
    for (int j = 0; j < 4; j++) {
        float uv = r[j];
        int c = 0;
        #pragma unroll
        for (int w = 32; w; w >>= 1)
            c += (cdfs[c + w - 1] <= uv) ? w : 0;
        float cb = cdfs[c - 1];
        float ca = cdfs[c];               // c==63 -> INF -> t==0, clamps to last mid
        float dnm = ca - cb;
        if (dnm < 1e-5f) dnm = 1.f;
        float t = __fdividef(uv - cb, dnm);
        fineS[ebase + j] = fmaf(__int2float_rn(c - 1) + t, step, M0);
    }
    __syncwarp();

    // ---- merge-path: arithmetic coarse (NEAR + i*step) + fine[128] -> 6 regs ----
    float m[6];
    {
        const int d0  = lane * 6;
        const int hib = min(d0, 64);
        int c = max(0, d0 - 128);
        #pragma unroll
        for (int w = 64; w; w >>= 1) {
            int idx = c + w - 1;
            float a = fmaf(__int2float_rn(idx), step, NEARv);
            float b = base[64 + d0 - 1 - idx];   // in-bounds; junk guarded below
            bool ok = (idx < hib) && (a <= b);
            c += ok ? w : 0;
        }
        int jb = d0 - c;                 // fine cursor (0..128)
        float fia = __int2float_rn(c);   // coarse cursor as float
        float a = fmaf(fia, step, NEARv);   // index 64 acts as natural sentinel
        float b = base[64 + jb];            // jb==128 -> INF sentinel
        #pragma unroll
        for (int t = 0; t < 6; t++) {
            bool ta = (a <= b);
            m[t] = ta ? a : b;
            fia += ta ? 1.0f : 0.0f;
            jb  += ta ? 0 : 1;
            a = fmaf(fia, step, NEARv);
            b = base[64 + jb];
        }
    }
    __syncwarp();   // all fine reads done; base[] safe to reuse

    float m6 = __shfl_down_sync(FULL, m[0], 1);

    // ---- densities: blocked, 3x LDG.64 per lane ----
    const float* dp = den + (size_t)ray * 192 + 6 * lane;
    float2 d01 = reinterpret_cast<const float2*>(dp)[0];
    float2 d23 = reinterpret_cast<const float2*>(dp + 2)[0];
    float2 d45 = reinterpret_cast<const float2*>(dp + 4)[0];

    float x0 = d01.x * (m[1] - m[0]);
    float x1 = x0 + d01.y * (m[2] - m[1]);
    float x2 = x1 + d23.x * (m[3] - m[2]);
    float x3 = x2 + d23.y * (m[4] - m[3]);
    float x4 = x3 + d45.x * (m[5] - m[4]);
    float lastDist = (lane == 31) ? 1e10f : (m6 - m[5]);
    float x5 = x4 + d45.y * lastDist;

    // Lane 31: exclude the artificial 1e10 term from the scan value
    // (prevents catastrophic cancellation in Sx; e5 still uses full x5 -> 0).
    float xs = (lane == 31) ? x4 : x5;

    float tinc = xs;
    #pragma unroll
    for (int off = 1; off < 32; off <<= 1) {
        float v = __shfl_up_sync(FULL, tinc, off);
        if (lane >= off) tinc += v;
    }
    float Sx = tinc - xs;   // exclusive prefix (sum of lanes < me)

    float e0p = __expf(-Sx);
    float e0 = __expf(-(Sx + x0));
    float e1 = __expf(-(Sx + x1));
    float e2 = __expf(-(Sx + x2));
    float e3 = __expf(-(Sx + x3));
    float e4 = __expf(-(Sx + x4));
    float e5 = __expf(-(Sx + x5));

    const int wb = 6 * lane;
    wsh[wb + 0] = e0p - e0;
    wsh[wb + 1] = e0 - e1;
    wsh[wb + 2] = e1 - e2;
    wsh[wb + 3] = e2 - e3;
    wsh[wb + 4] = e3 - e4;
    wsh[wb + 5] = e4 - e5;
    __syncwarp();

    // ---- color accumulation: coalesced loads, div-free weight indexing ----
    // j = 32t + lane; floor(j/3) = 10t + (2t)/3 + L + carry
    const int L  = lane / 3;          // lane = 3L + p
    const int p  = lane - 3 * L;
    const float* wp0 = wsh + L;                 // R=0: carry 0
    const float* wp1 = wsh + L + (p >= 1);      // R=2: carry = (p>=1)
    const float* wp2 = wsh + L + (p >= 2);      // R=1: carry = (p>=2)

    const float* colp = col + (size_t)ray * 576;
    float a0 = 0.f, a1 = 0.f, a2 = 0.f;
    #pragma unroll
    for (int t = 0; t < 18; t++) {
        float v = colp[32 * t + lane];
        const int R = (2 * t) % 3;              // compile-time
        const int C = 10 * t + (2 * t) / 3;     // compile-time
        float wv = (R == 0) ? wp0[C] : ((R == 1) ? wp2[C] : wp1[C]);
        if (R == 0) a0 += wv * v;
        else if (R == 1) a1 += wv * v;
        else a2 += wv * v;
    }

    // lane's a[k] holds channel (p + k) % 3
    float rr = (p == 0) ? a0 : ((p == 1) ? a2 : a1);
    float gg = (p == 0) ? a1 : ((p == 1) ? a0 : a2);
    float bb = (p == 0) ? a2 : ((p == 1) ? a1 : a0);

    #pragma unroll
    for (int off = 16; off; off >>= 1) {
        rr += __shfl_down_sync(FULL, rr, off);
        gg += __shfl_down_sync(FULL, gg, off);
        bb += __shfl_down_sync(FULL, bb, off);
    }
    if (lane == 0) {
        out[(size_t)ray * 3 + 0] = rr;
        out[(size_t)ray * 3 + 1] = gg;
        out[(size_t)ray * 3 + 2] = bb;
    }
}

extern "C" void kernel_launch(void* const* d_in, const int* in_sizes, int n_in,
                              void* d_out, int out_size)
{
    const float* cdv = (const float*)d_in[2];
    const float* cw  = (const float*)d_in[3];
    const float* u   = (const float*)d_in[4];
    const float* den = (const float*)d_in[5];
    const float* col = (const float*)d_in[6];
    float* out = (float*)d_out;
    const int B = in_sizes[0] / 3;

    const int warpsPerBlock = 8;
    const int blocks = (B + warpsPerBlock - 1) / warpsPerBlock;
    render_ray_kernel<<<blocks, warpsPerBlock * 32>>>(cdv, cw, u, den, col, out, B);
}

// round 16
// speedup vs baseline: 1.1241x; 1.0275x over previous
#include <cuda_runtime.h>
#include <math_constants.h>

#define FULL 0xffffffffu

// One warp per ray, 8 warps/block.
// Per-warp smem words: [0..62]=cdf, [63]=INF pad, [64..255]=merged(192), [256]=pad.
// After composite reads, [0..191] reused as per-sample weights.
__global__ __launch_bounds__(256) void render_ray_kernel(
    const float* __restrict__ cdv,   // [B,64] uniform grid NEAR + k*step
    const float* __restrict__ cw,    // [B,64]
    const float* __restrict__ uin,   // [B,128]
    const float* __restrict__ den,   // [B,192]
    const float* __restrict__ col,   // [B,192,3]
    float* __restrict__ out,         // [B,3]
    int B)
{
    const int warp = threadIdx.x >> 5;
    const int lane = threadIdx.x & 31;
    const int ray  = blockIdx.x * 8 + warp;
    if (ray >= B) return;

    __shared__ float sh[8][264];
    float* base = sh[warp];
    float* cdfs = base;           // cdf[0..62], [63]=INF pad
    float* mrg  = base + 64;      // merged[0..191], pad at [192]
    float* wsh  = base;           // 192 weights (reuse after merged reads)

    // ---- uniform grid params: only cdv[0], cdv[1] needed ----
    float2 c2 = make_float2(0.f, 0.f);
    if (lane == 0) c2 = *reinterpret_cast<const float2*>(cdv + (size_t)ray * 64);
    const float NEARv = __shfl_sync(FULL, c2.x, 0);
    const float step  = __shfl_sync(FULL, c2.y, 0) - NEARv;
    const float M0    = NEARv + 0.5f * step;     // mids[k] = M0 + k*step
    if (lane == 0) cdfs[63] = CUDART_INF_F;      // cdf pad for unguarded search

    // ---- sentinel-init merged array (conflict-free, 6 wavefronts + pad) ----
    #pragma unroll
    for (int k2 = 0; k2 < 6; k2++) mrg[lane + 32 * k2] = CUDART_INF_F;
    if (lane == 0) mrg[192] = CUDART_INF_F;

    // ---- weights -> normalized CDF (62 pdf entries, cdf[0..62]) ----
    const float* cwp = cw + (size_t)ray * 64;
    float w0 = 0.f, w1 = 0.f;
    if (lane < 31) {
        w0 = cwp[1 + 2 * lane] + 1e-5f;
        w1 = cwp[2 + 2 * lane] + 1e-5f;
    }
    float s2 = w0 + w1;
    float inc = s2;
    #pragma unroll
    for (int off = 1; off < 32; off <<= 1) {
        float v = __shfl_up_sync(FULL, inc, off);
        if (lane >= off) inc += v;
    }
    float total = __shfl_sync(FULL, inc, 31);
    float excl0 = inc - s2;
    float rt    = __fdividef(1.0f, total);
    if (lane == 0) cdfs[0] = 0.f;
    if (lane < 31) {
        cdfs[2 * lane + 1] = (excl0 + w0) * rt;
        cdfs[2 * lane + 2] = (excl0 + w0 + w1) * rt;
    }

    // ---- load u (4/lane blocked) and bitonic sort 128 ----
    const float4 u4 = reinterpret_cast<const float4*>(uin + (size_t)ray * 128)[lane];
    float r[4] = { u4.x, u4.y, u4.z, u4.w };
    const int ebase = lane * 4;

    #pragma unroll
    for (int k = 2; k <= 128; k <<= 1) {
        #pragma unroll
        for (int d = k >> 1; d > 0; d >>= 1) {
            if (d >= 4) {
                const bool flip = (((ebase & k) == 0) != ((ebase & d) != 0));
                #pragma unroll
                for (int j = 0; j < 4; j++) {
                    float o = __shfl_xor_sync(FULL, r[j], d >> 2);
                    r[j] = flip ? fminf(r[j], o) : fmaxf(r[j], o);
                }
            } else {
                #pragma unroll
                for (int j = 0; j < 4; j++) {
                    int jp = j ^ d;
                    if (jp > j) {
                        bool asc = (((ebase + j) & k) == 0);
                        float lo2 = fminf(r[j], r[jp]);
                        float hi2 = fmaxf(r[j], r[jp]);
                        r[j]  = asc ? lo2 : hi2;
                        r[jp] = asc ? hi2 : lo2;
                    }
                }
            }
        }
    }

    __syncwarp();  // cdf + merged-init visible

    // ---- inverse CDF + direct scatter into merged position ----
    // f = M0 + (c-1+t)*step;  #coarse < f  =  c + (t >= 0.5)
    // merged_idx = j_global + c + (t >= 0.5)   (strictly increasing in j)
    #pragma unroll
    for (int j = 0; j < 4; j++) {
        float uv = r[j];
        int c = 0;
        #pragma unroll
        for (int w = 32; w; w >>= 1)
            c += (cdfs[c + w - 1] <= uv) ? w : 0;
        float cb = cdfs[c - 1];
        float ca = cdfs[c];               // c==63 -> INF -> t==0, clamps to last mid
        float dnm = ca - cb;
        if (dnm < 1e-5f) dnm = 1.f;
        float t = __fdividef(uv - cb, dnm);
        float f = fmaf(__int2float_rn(c - 1) + t, step, M0);
        int idx = ebase + j + c + (t >= 0.5f);
        mrg[idx] = f;
    }
    __syncwarp();

    // ---- gather 7 contiguous slots; fill empties with arithmetic coarse ----
    // e-th empty slot overall holds coarse_e = NEAR + e*step.
    const int d0 = 6 * lane;
    float mv[7];
    #pragma unroll
    for (int t = 0; t < 7; t++) mv[t] = mrg[d0 + t];

    int cnt = 0;
    #pragma unroll
    for (int t = 0; t < 6; t++) cnt += (mv[t] == CUDART_INF_F) ? 1 : 0;

    int isc = cnt;                       // warp exclusive scan of empty counts
    #pragma unroll
    for (int off = 1; off < 32; off <<= 1) {
        int v = __shfl_up_sync(FULL, isc, off);
        if (lane >= off) isc += v;
    }
    int e = isc - cnt;                   // empties before my region

    #pragma unroll
    for (int t = 0; t < 7; t++) {        // slot 6 fill uses e after my 6 slots
        bool emp = (mv[t] == CUDART_INF_F);
        mv[t] = emp ? fmaf(__int2float_rn(e), step, NEARv) : mv[t];
        e += emp ? 1 : 0;
    }
    __syncwarp();   // all merged reads done; base[] safe to reuse for weights

    // ---- densities: blocked, 3x LDG.64 per lane ----
    const float* dp = den + (size_t)ray * 192 + 6 * lane;
    float2 d01 = reinterpret_cast<const float2*>(dp)[0];
    float2 d23 = reinterpret_cast<const float2*>(dp + 2)[0];
    float2 d45 = reinterpret_cast<const float2*>(dp + 4)[0];

    float x0 = d01.x * (mv[1] - mv[0]);
    float x1 = x0 + d01.y * (mv[2] - mv[1]);
    float x2 = x1 + d23.x * (mv[3] - mv[2]);
    float x3 = x2 + d23.y * (mv[4] - mv[3]);
    float x4 = x3 + d45.x * (mv[5] - mv[4]);
    float lastDist = (lane == 31) ? 1e10f : (mv[6] - mv[5]);
    float x5 = x4 + d45.y * lastDist;

    // Lane 31: exclude the artificial 1e10 term from the scan value
    // (prevents catastrophic cancellation in Sx; e5 still uses full x5 -> 0).
    float xs = (lane == 31) ? x4 : x5;

    float tinc = xs;
    #pragma unroll
    for (int off = 1; off < 32; off <<= 1) {
        float v = __shfl_up_sync(FULL, tinc, off);
        if (lane >= off) tinc += v;
    }
    float Sx = tinc - xs;   // exclusive prefix (sum of lanes < me)

    float e0p = __expf(-Sx);
    float e0 = __expf(-(Sx + x0));
    float e1 = __expf(-(Sx + x1));
    float e2 = __expf(-(Sx + x2));
    float e3 = __expf(-(Sx + x3));
    float e4 = __expf(-(Sx + x4));
    float e5 = __expf(-(Sx + x5));

    const int wb = 6 * lane;
    wsh[wb + 0] = e0p - e0;
    wsh[wb + 1] = e0 - e1;
    wsh[wb + 2] = e1 - e2;
    wsh[wb + 3] = e2 - e3;
    wsh[wb + 4] = e3 - e4;
    wsh[wb + 5] = e4 - e5;
    __syncwarp();

    // ---- color accumulation: coalesced loads, div-free weight indexing ----
    // j = 32t + lane; floor(j/3) = 10t + (2t)/3 + L + carry
    const int L  = lane / 3;          // lane = 3L + p
    const int p  = lane - 3 * L;
    const float* wp0 = wsh + L;                 // R=0: carry 0
    const float* wp1 = wsh + L + (p >= 1);      // R=2: carry = (p>=1)
    const float* wp2 = wsh + L + (p >= 2);      // R=1: carry = (p>=2)

    const float* colp = col + (size_t)ray * 576;
    float a0 = 0.f, a1 = 0.f, a2 = 0.f;
    #pragma unroll
    for (int t = 0; t < 18; t++) {
        float v = colp[32 * t + lane];
        const int R = (2 * t) % 3;              // compile-time
        const int C = 10 * t + (2 * t) / 3;     // compile-time
        float wv = (R == 0) ? wp0[C] : ((R == 1) ? wp2[C] : wp1[C]);
        if (R == 0) a0 += wv * v;
        else if (R == 1) a1 += wv * v;
        else a2 += wv * v;
    }

    // lane's a[k] holds channel (p + k) % 3
    float rr = (p == 0) ? a0 : ((p == 1) ? a2 : a1);
    float gg = (p == 0) ? a1 : ((p == 1) ? a0 : a2);
    float bb = (p == 0) ? a2 : ((p == 1) ? a1 : a0);

    #pragma unroll
    for (int off = 16; off; off >>= 1) {
        rr += __shfl_down_sync(FULL, rr, off);
        gg += __shfl_down_sync(FULL, gg, off);
        bb += __shfl_down_sync(FULL, bb, off);
    }
    if (lane == 0) {
        out[(size_t)ray * 3 + 0] = rr;
        out[(size_t)ray * 3 + 1] = gg;
        out[(size_t)ray * 3 + 2] = bb;
    }
}

extern "C" void kernel_launch(void* const* d_in, const int* in_sizes, int n_in,
                              void* d_out, int out_size)
{
    const float* cdv = (const float*)d_in[2];
    const float* cw  = (const float*)d_in[3];
    const float* u   = (const float*)d_in[4];
    const float* den = (const float*)d_in[5];
    const float* col = (const float*)d_in[6];
    float* out = (float*)d_out;
    const int B = in_sizes[0] / 3;

    const int warpsPerBlock = 8;
    const int blocks = (B + warpsPerBlock - 1) / warpsPerBlock;
    render_ray_kernel<<<blocks, warpsPerBlock * 32>>>(cdv, cw, u, den, col, out, B);
}